// round 5
// baseline (speedup 1.0000x reference)
#include <cuda_runtime.h>

// Chamfer distance, B=2, N=8192, Gaussian 3D points — exact grid-accelerated NN.
// 32^3 cell grid over [-5,5]^3, counting sort, warp-per-query expanding-box search.
// Bound: any point outside Chebyshev cell-box r is > r*h away (conservative under clamp).
// h-form: minimize h_j = 0.5||p||^2 - q.p ; dsq = max(2h+||q||^2, 0); sqrt after min.

#define BATCH  2
#define NPTS   8192
#define G      32
#define NCELL  (G * G * G)          // 32768
#define NSET   4                    // s: 0=pred b0, 1=pred b1, 2=gt b0, 3=gt b1
#define HCELL  (10.0f / G)          // 0.3125
#define INVH   (G / 10.0f)          // 3.2

__device__ int    g_cnt[NSET * NCELL];        // zero-init; re-zeroed by nn kernel each call
__device__ int    g_off[NSET * (NCELL + 1)];
__device__ int    g_cur[NSET * NCELL];
__device__ float4 g_sorted[NSET * NPTS];
__device__ float  g_dist[4 * NPTS];           // best sq-dist per query task
__device__ float  g_result_unused[1];

__device__ __forceinline__ int cell1(float x) {
    int c = (int)floorf((x + 5.0f) * INVH);
    return min(max(c, 0), G - 1);
}

__global__ __launch_bounds__(256)
void count_kernel(const float* __restrict__ pred, const float* __restrict__ gt) {
    int tid = blockIdx.x * 256 + threadIdx.x;      // < NSET*NPTS
    int s = tid >> 13, i = tid & (NPTS - 1);
    const float* src = (s < 2 ? pred : gt) + ((size_t)(s & 1) * NPTS + i) * 3;
    int cx = cell1(src[0]), cy = cell1(src[1]), cz = cell1(src[2]);
    atomicAdd(&g_cnt[s * NCELL + (cx * G + cy) * G + cz], 1);
}

__global__ __launch_bounds__(1024)
void scan_kernel() {
    const int s = blockIdx.x;
    const int t = threadIdx.x;
    __shared__ int sh[1024];
    const int base = s * NCELL;
    int local[32];
    int sum = 0;
#pragma unroll
    for (int i = 0; i < 32; i++) { local[i] = g_cnt[base + t * 32 + i]; sum += local[i]; }
    sh[t] = sum;
    __syncthreads();
    for (int d = 1; d < 1024; d <<= 1) {
        int v = (t >= d) ? sh[t - d] : 0;
        __syncthreads();
        sh[t] += v;
        __syncthreads();
    }
    int run = sh[t] - sum;   // exclusive base
    const int obase = s * (NCELL + 1);
#pragma unroll
    for (int i = 0; i < 32; i++) {
        g_off[obase + t * 32 + i] = run;
        g_cur[base + t * 32 + i]  = run;
        run += local[i];
    }
    if (t == 1023) g_off[obase + NCELL] = run;   // = NPTS
}

__global__ __launch_bounds__(256)
void scatter_kernel(const float* __restrict__ pred, const float* __restrict__ gt) {
    int tid = blockIdx.x * 256 + threadIdx.x;
    int s = tid >> 13, i = tid & (NPTS - 1);
    const float* src = (s < 2 ? pred : gt) + ((size_t)(s & 1) * NPTS + i) * 3;
    float x = src[0], y = src[1], z = src[2];
    int cell = (cell1(x) * G + cell1(y)) * G + cell1(z);
    int pos = atomicAdd(&g_cur[s * NCELL + cell], 1);
    g_sorted[s * NPTS + pos] = make_float4(x, y, z, 0.5f * (x * x + y * y + z * z));
}

// Warp-per-query exact NN. 4*NPTS = 32768 query tasks -> 4096 CTAs x 8 warps.
__global__ __launch_bounds__(256)
void nn_kernel() {
    const int gw   = blockIdx.x * 8 + (threadIdx.x >> 5);   // 0..32767
    const int lane = threadIdx.x & 31;
    const int u   = gw >> 13;            // dir*2 + b
    const int qi  = gw & (NPTS - 1);
    const int dir = u >> 1, b = u & 1;
    const int qset = dir == 0 ? 2 + b : b;       // dir0: queries=gt, refs=pred
    const int rset = dir == 0 ? b : 2 + b;

    const float4 q = g_sorted[qset * NPTS + qi];
    const float4* __restrict__ R  = g_sorted + rset * NPTS;
    const int*    __restrict__ off = g_off + rset * (NCELL + 1);

    const int cx = cell1(q.x), cy = cell1(q.y), cz = cell1(q.z);
    const float qsq = 2.0f * q.w;   // ||q||^2
    float bh = 3.4e38f;

    // ---- r = 1 fast path: 9 rows, offsets fetched lane-parallel ----
    {
        const int z0 = max(cz - 1, 0), z1 = min(cz + 1, G - 1);
        int rs = 0, re = 0;
        if (lane < 9) {
            int dx = cx + lane / 3 - 1, dy = cy + lane % 3 - 1;
            if (dx >= 0 && dx < G && dy >= 0 && dy < G) {
                int bc = (dx * G + dy) * G;
                rs = off[bc + z0];
                re = off[bc + z1 + 1];
            }
        }
#pragma unroll 1
        for (int row = 0; row < 9; row++) {
            int s = __shfl_sync(0xffffffffu, rs, row);
            int e = __shfl_sync(0xffffffffu, re, row);
            for (int t = s + lane; t < e; t += 32) {
                float4 p = R[t];
                float h = fmaf(-q.x, p.x, fmaf(-q.y, p.y, fmaf(-q.z, p.z, p.w)));
                bh = fminf(bh, h);
            }
        }
        float w = bh;
#pragma unroll
        for (int o = 16; o; o >>= 1) w = fminf(w, __shfl_xor_sync(0xffffffffu, w, o));
        float bd2 = fmaxf(fmaf(2.0f, w, qsq), 0.0f);
        float rb = 1.0f * HCELL;
        if (bd2 <= rb * rb) {
            if (lane == 0) g_dist[gw] = bd2;
            goto done;
        }
    }

    // ---- generic expanding boxes, r >= 2 (rare) ----
    for (int r = 2; r <= G; r++) {
        const int x0 = max(cx - r, 0), x1 = min(cx + r, G - 1);
        const int y0 = max(cy - r, 0), y1 = min(cy + r, G - 1);
        const int z0 = max(cz - r, 0), z1 = min(cz + r, G - 1);
        for (int dx = x0; dx <= x1; dx++) {
            for (int dy = y0; dy <= y1; dy++) {
                int bc = (dx * G + dy) * G;
                int s = off[bc + z0], e = off[bc + z1 + 1];
                for (int t = s + lane; t < e; t += 32) {
                    float4 p = R[t];
                    float h = fmaf(-q.x, p.x, fmaf(-q.y, p.y, fmaf(-q.z, p.z, p.w)));
                    bh = fminf(bh, h);
                }
            }
        }
        float w = bh;
#pragma unroll
        for (int o = 16; o; o >>= 1) w = fminf(w, __shfl_xor_sync(0xffffffffu, w, o));
        float bd2 = fmaxf(fmaf(2.0f, w, qsq), 0.0f);
        float rb = (float)r * HCELL;
        if (bd2 <= rb * rb || r == G) {
            if (lane == 0) g_dist[gw] = bd2;
            break;
        }
    }

done:
    // Re-zero counts for the next graph replay (counts are dead after scan_kernel).
    // 4096 blocks x 32 slots = NSET*NCELL exactly.
    if (threadIdx.x < 32) g_cnt[blockIdx.x * 32 + threadIdx.x] = 0;
}

// Final: single block, fixed-order (deterministic) sum of sqrt over all 32768 tasks.
__global__ __launch_bounds__(1024)
void reduce_kernel(float* __restrict__ out) {
    __shared__ float sh[1024];
    float acc = 0.0f;
    for (int i = threadIdx.x; i < 4 * NPTS; i += 1024) acc += sqrtf(g_dist[i]);
    sh[threadIdx.x] = acc;
    __syncthreads();
    for (int s = 512; s > 0; s >>= 1) {
        if (threadIdx.x < s) sh[threadIdx.x] += sh[threadIdx.x + s];
        __syncthreads();
    }
    if (threadIdx.x == 0) out[0] = sh[0] / (float)(BATCH * NPTS);
}

extern "C" void kernel_launch(void* const* d_in, const int* in_sizes, int n_in,
                              void* d_out, int out_size) {
    const float* pred = (const float*)d_in[0];
    const float* gt   = (const float*)d_in[1];
    float* out        = (float*)d_out;

    count_kernel  <<<(NSET * NPTS) / 256, 256>>>(pred, gt);
    scan_kernel   <<<NSET, 1024>>>();
    scatter_kernel<<<(NSET * NPTS) / 256, 256>>>(pred, gt);
    nn_kernel     <<<(4 * NPTS) / 8, 256>>>();
    reduce_kernel <<<1, 1024>>>(out);
}

// round 6
// speedup vs baseline: 3.6324x; 3.6324x over previous
#include <cuda_runtime.h>

// Chamfer distance, B=2, N=8192. Symmetric brute force: each pair computed ONCE,
// feeding BOTH row-min (dist1: per-gt) and col-min (dist2: per-pred).
// w_ij = c_i + c_j - q_i.p_j (c = 0.5||.||^2); dist^2 = max(2w, 0); sqrt after min.
// Inner: per 2 pairs = 1 FADD2 + 3 FFMA2 (fma pipe) + 4 FMNMX (alu pipe).

#define BATCH   2
#define NPTS    8192
#define THREADS 128
#define ITILE   4
#define IBLK    (THREADS * ITILE)   // 512 gt rows per CTA
#define JBLK    256                 // pred cols per CTA
#define JPAIRS  (JBLK / 2)          // 128
#define ITILES  (NPTS / IBLK)       // 16
#define JTILES  (NPTS / JBLK)       // 32
#define NCTA    (BATCH * ITILES * JTILES)  // 1024

// Partial mins. rowpart[(b*JTILES+jt)*NPTS + i], colpart[(b*ITILES+it)*NPTS + j].
__device__ float g_rowpart[BATCH * JTILES * NPTS];   // 2 MB
__device__ float g_colpart[BATCH * ITILES * NPTS];   // 1 MB
__device__ float g_blocksum[128];

typedef unsigned long long u64;

__device__ __forceinline__ u64 pack2(float lo, float hi) {
    u64 d; asm("mov.b64 %0, {%1,%2};" : "=l"(d) : "f"(lo), "f"(hi)); return d;
}
__device__ __forceinline__ void unpack2(u64 d, float& lo, float& hi) {
    asm("mov.b64 {%0,%1}, %2;" : "=f"(lo), "=f"(hi) : "l"(d));
}
__device__ __forceinline__ u64 fma2(u64 a, u64 b, u64 c) {
    u64 d; asm("fma.rn.f32x2 %0, %1, %2, %3;" : "=l"(d) : "l"(a), "l"(b), "l"(c));
    return d;
}
__device__ __forceinline__ u64 add2(u64 a, u64 b) {
    u64 d; asm("add.rn.f32x2 %0, %1, %2;" : "=l"(d) : "l"(a), "l"(b));
    return d;
}

__global__ __launch_bounds__(THREADS, 7)
void chamfer_pass(const float* __restrict__ pred, const float* __restrict__ gt) {
    const int bid = blockIdx.x;
    const int b   = bid >> 9;
    const int r   = bid & 511;
    const int it  = r >> 5;          // 0..15
    const int jt  = r & 31;          // 0..31
    const int ibase = it * IBLK;
    const int jbase = jt * JBLK;
    const int tid = threadIdx.x;

    // j-side (pred) staged pair-packed: sxy={x0,x1,y0,y1}, szc={z0,z1,c0,c1}
    __shared__ float4 sxy[JPAIRS];
    __shared__ float4 szc[JPAIRS];
    __shared__ float2 scm[4][JPAIRS];   // per-warp col-min rows

    {
        const float* p = pred + ((size_t)b * NPTS + jbase + 2 * tid) * 3;
        float x0 = p[0], y0 = p[1], z0 = p[2];
        float x1 = p[3], y1 = p[4], z1 = p[5];
        sxy[tid] = make_float4(x0, x1, y0, y1);
        szc[tid] = make_float4(z0, z1,
                               0.5f * (x0 * x0 + y0 * y0 + z0 * z0),
                               0.5f * (x1 * x1 + y1 * y1 + z1 * z1));
    }
#pragma unroll
    for (int u = 0; u < 4; u++)
        scm[u][tid] = make_float2(3.4e38f, 3.4e38f);

    // i-side (gt) in registers, negated + replicated for f32x2.
    u64 nix2[ITILE], niy2[ITILE], niz2[ITILE], ci2[ITILE];
    float rmA[ITILE], rmB[ITILE];
#pragma unroll
    for (int k = 0; k < ITILE; k++) {
        const float* g = gt + ((size_t)b * NPTS + ibase + tid + k * THREADS) * 3;
        float x = g[0], y = g[1], z = g[2];
        nix2[k] = pack2(-x, -x);
        niy2[k] = pack2(-y, -y);
        niz2[k] = pack2(-z, -z);
        float c = 0.5f * (x * x + y * y + z * z);
        ci2[k] = pack2(c, c);
        rmA[k] = 3.4e38f;
        rmB[k] = 3.4e38f;
    }
    __syncthreads();

    const int w    = tid >> 5;
    const int lane = tid & 31;
    const ulonglong2* __restrict__ pxy = reinterpret_cast<const ulonglong2*>(sxy);
    const ulonglong2* __restrict__ pzc = reinterpret_cast<const ulonglong2*>(szc);
    float2* __restrict__ cmrow = scm[w];

    // Lane-skewed jp order: at step s, lanes hold distinct jp -> race-free col RMW.
    int jp = lane;
#pragma unroll 2
    for (int s = 0; s < JPAIRS; s++) {
        ulonglong2 vxy = pxy[jp];       // {x0,x1},{y0,y1}
        ulonglong2 vzc = pzc[jp];       // {z0,z1},{c0,c1}
        float2 cm = cmrow[jp];
        float ca0 = cm.x, ca1 = cm.y;
#pragma unroll
        for (int k = 0; k < ITILE; k++) {
            u64 w2 = fma2(niz2[k], vzc.x, add2(ci2[k], vzc.y));
            w2 = fma2(niy2[k], vxy.y, w2);
            w2 = fma2(nix2[k], vxy.x, w2);
            float w0, w1; unpack2(w2, w0, w1);
            rmA[k] = fminf(rmA[k], w0);
            rmB[k] = fminf(rmB[k], w1);
            ca0 = fminf(ca0, w0);
            ca1 = fminf(ca1, w1);
        }
        cmrow[jp] = make_float2(ca0, ca1);
        jp = (jp + 1) & (JPAIRS - 1);
    }
    __syncthreads();

    // Row-min partials (min_j w), coalesced.
    float* rout = g_rowpart + ((size_t)(b * JTILES + jt)) * NPTS + ibase;
#pragma unroll
    for (int k = 0; k < ITILE; k++)
        rout[tid + k * THREADS] = fminf(rmA[k], rmB[k]);

    // Col-min partials: combine the 4 warp rows, write float2 coalesced.
    {
        float2 m = scm[0][tid];
#pragma unroll
        for (int u = 1; u < 4; u++) {
            float2 v = scm[u][tid];
            m.x = fminf(m.x, v.x);
            m.y = fminf(m.y, v.y);
        }
        float2* cout = reinterpret_cast<float2*>(
            g_colpart + ((size_t)(b * ITILES + it)) * NPTS + jbase);
        cout[tid] = m;
    }
}

// Stage 1: 32768 tasks. First 16384 = row side (min over 32 jt), rest = col side
// (min over 16 it). dist^2 = max(2*min_w, 0); sqrt; fixed-order block sum.
__global__ __launch_bounds__(256)
void chamfer_reduce_a() {
    __shared__ float ssum[256];
    const int qid = blockIdx.x * 256 + threadIdx.x;   // 0..32767
    float mv = 3.4e38f;
    if (qid < BATCH * NPTS) {
        const int b = qid >> 13, i = qid & (NPTS - 1);
        const float* p = g_rowpart + (size_t)b * JTILES * NPTS + i;
#pragma unroll
        for (int t = 0; t < JTILES; t++) mv = fminf(mv, p[(size_t)t * NPTS]);
    } else {
        const int q = qid - BATCH * NPTS;
        const int b = q >> 13, j = q & (NPTS - 1);
        const float* p = g_colpart + (size_t)b * ITILES * NPTS + j;
#pragma unroll
        for (int t = 0; t < ITILES; t++) mv = fminf(mv, p[(size_t)t * NPTS]);
    }
    ssum[threadIdx.x] = sqrtf(fmaxf(2.0f * mv, 0.0f));
    __syncthreads();
    for (int s = 128; s > 0; s >>= 1) {
        if (threadIdx.x < s) ssum[threadIdx.x] += ssum[threadIdx.x + s];
        __syncthreads();
    }
    if (threadIdx.x == 0) g_blocksum[blockIdx.x] = ssum[0];
}

__global__ void chamfer_reduce_b(float* __restrict__ out) {
    __shared__ float s[128];
    s[threadIdx.x] = g_blocksum[threadIdx.x];
    __syncthreads();
    for (int st = 64; st > 0; st >>= 1) {
        if (threadIdx.x < st) s[threadIdx.x] += s[threadIdx.x + st];
        __syncthreads();
    }
    if (threadIdx.x == 0) out[0] = s[0] / (float)(BATCH * NPTS);
}

extern "C" void kernel_launch(void* const* d_in, const int* in_sizes, int n_in,
                              void* d_out, int out_size) {
    const float* pred = (const float*)d_in[0];
    const float* gt   = (const float*)d_in[1];
    float* out        = (float*)d_out;

    chamfer_pass<<<NCTA, THREADS>>>(pred, gt);
    chamfer_reduce_a<<<128, 256>>>();
    chamfer_reduce_b<<<1, 128>>>(out);
}